// round 3
// baseline (speedup 1.0000x reference)
#include <cuda_runtime.h>
#include <math.h>

#define IMG_H 1080
#define IMG_W 1920
#define HW (IMG_H * IMG_W)

// Scratch (no cudaMalloc allowed)
__device__ float4   g_buf4[HW];   // accumulated (r, g, b, z)
__device__ float    g_bufw[HW];   // accumulated weight
__device__ unsigned g_zbuf[HW];   // z-buffer as uint bits (positive floats are order-preserving)

__global__ void init_kernel() {
    int i = blockIdx.x * blockDim.x + threadIdx.x;
    if (i < HW) {
        g_buf4[i] = make_float4(0.f, 0.f, 0.f, 0.f);
        g_bufw[i] = 0.f;
        g_zbuf[i] = 0x7f800000u;  // +inf
    }
}

__device__ __forceinline__ bool project(
    const float* __restrict__ vm, const float* __restrict__ Km,
    float mx, float my, float mz,
    float& x, float& y, float& z)
{
    z = vm[8] * mx + vm[9] * my + vm[10] * mz + vm[11];
    if (!(z > 0.1f)) return false;
    float cxm = vm[0] * mx + vm[1] * my + vm[2] * mz + vm[3];
    float cym = vm[4] * mx + vm[5] * my + vm[6] * mz + vm[7];
    float fx = Km[0], cx = Km[2], fy = Km[4], cy = Km[5];
    x = cxm * fx / z + cx;
    y = cym * fy / z + cy;
    // on = front & x>=0 & x<W-1 & y>=0 & y<H-1
    return (x >= 0.f) & (x < (float)(IMG_W - 1)) & (y >= 0.f) & (y < (float)(IMG_H - 1));
}

__global__ void zmin_kernel(const float* __restrict__ means,
                            const float* __restrict__ vm,
                            const float* __restrict__ Km, int n)
{
    int i = blockIdx.x * blockDim.x + threadIdx.x;
    if (i >= n) return;
    float mx = means[3 * i], my = means[3 * i + 1], mz = means[3 * i + 2];
    float x, y, z;
    if (!project(vm, Km, mx, my, mz, x, y, z)) return;
    int x0 = (int)floorf(x);
    int y0 = (int)floorf(y);
    atomicMin(&g_zbuf[y0 * IMG_W + x0], __float_as_uint(z));
}

__device__ __forceinline__ float sigmoidf(float v) {
    return 1.f / (1.f + expf(-v));
}

__global__ void splat_kernel(const float* __restrict__ means,
                             const float* __restrict__ colors,
                             const float* __restrict__ vm,
                             const float* __restrict__ Km, int n)
{
    int i = blockIdx.x * blockDim.x + threadIdx.x;
    if (i >= n) return;
    float mx = means[3 * i], my = means[3 * i + 1], mz = means[3 * i + 2];
    float x, y, z;
    if (!project(vm, Km, mx, my, mz, x, y, z)) return;

    float x0f = floorf(x), y0f = floorf(y);
    int x0 = (int)x0f, y0 = (int)y0f;
    int pix = y0 * IMG_W + x0;

    float zref = __uint_as_float(g_zbuf[pix]);
    if (!(z <= zref + 0.05f)) return;

    float dx = x - x0f, dy = y - y0f;
    float wa = (1.f - dx) * (1.f - dy);
    float wb = dx * (1.f - dy);
    float wc = (1.f - dx) * dy;
    float wd = dx * dy;

    float r = sigmoidf(colors[3 * i]);
    float g = sigmoidf(colors[3 * i + 1]);
    float b = sigmoidf(colors[3 * i + 2]);

    int x1 = x0 + 1;           // on-test guarantees in-bounds
    int y1 = y0 + 1;
    int pb = y1 * IMG_W + x0;  // reference applies wb here
    int pc = y0 * IMG_W + x1;  // reference applies wc here
    int pd = y1 * IMG_W + x1;

    // 4 corners, matching reference's (idx, w) pairing exactly
    atomicAdd(&g_buf4[pix], make_float4(r * wa, g * wa, b * wa, z * wa));
    atomicAdd(&g_bufw[pix], wa);
    atomicAdd(&g_buf4[pb],  make_float4(r * wb, g * wb, b * wb, z * wb));
    atomicAdd(&g_bufw[pb],  wb);
    atomicAdd(&g_buf4[pc],  make_float4(r * wc, g * wc, b * wc, z * wc));
    atomicAdd(&g_bufw[pc],  wc);
    atomicAdd(&g_buf4[pd],  make_float4(r * wd, g * wd, b * wd, z * wd));
    atomicAdd(&g_bufw[pd],  wd);
}

__global__ void norm_kernel(float4* __restrict__ out)
{
    int i = blockIdx.x * blockDim.x + threadIdx.x;
    if (i >= HW) return;
    float4 acc = g_buf4[i];
    float inv = 1.f / (g_bufw[i] + 1e-6f);
    float4 o;
    o.x = fminf(fmaxf(acc.x * inv, 0.f), 1.f);
    o.y = fminf(fmaxf(acc.y * inv, 0.f), 1.f);
    o.z = fminf(fmaxf(acc.z * inv, 0.f), 1.f);
    o.w = acc.w * inv;
    out[i] = o;
}

extern "C" void kernel_launch(void* const* d_in, const int* in_sizes, int n_in,
                              void* d_out, int out_size)
{
    const float* means  = (const float*)d_in[0];
    const float* colors = (const float*)d_in[1];
    // d_in[2] opacities, d_in[3] scales, d_in[4] quats: unused by reference output
    const float* vm = (const float*)d_in[5];
    const float* Km = (const float*)d_in[6];

    int n = in_sizes[0] / 3;

    const int B = 256;
    init_kernel<<<(HW + B - 1) / B, B>>>();
    zmin_kernel<<<(n + B - 1) / B, B>>>(means, vm, Km, n);
    splat_kernel<<<(n + B - 1) / B, B>>>(means, colors, vm, Km, n);
    norm_kernel<<<(HW + B - 1) / B, B>>>((float4*)d_out);
}